// round 14
// baseline (speedup 1.0000x reference)
#include <cuda_runtime.h>
#include <cuda_fp16.h>
#include <cstdint>
#include <cstddef>

// Problem sizes
#define HH     256
#define BB     256
#define TT     512
#define DD     64
#define NCLASS 10

// Topology: 16 clusters x 8 CTAs; cluster owns 16 batch rows; CTA owns 32 j.
#define CS   8
#define NC   16
#define BC   16
#define RTH  512   // 16 warps: warp = (mt = w&7, kh = w>>3)
#define NKT  20    // k-tiles: 16 for H=256 (kt 0..15), 4 for D=64 (kt 16..19)
#define KHT  10    // k-tiles per k-half warp (interleaved: kt = kh + 2*ktl)

// ---- SMEM layout (bytes) ----
#define SM_AL  0
#define SM_XHI (SM_AL + 8 * NKT * 512)
#define SM_XLO (SM_XHI + 2 * 512 * 4)
#define SM_Z0  (SM_XLO + 2 * 512 * 4)
#define SM_Z1  (SM_Z0 + 128 * 18 * 4)
#define SM_MB  (SM_Z1 + 128 * 18 * 4)     // fullA @ +0, fullB @ +8, empty @ +16
#define SM_TOTAL (SM_MB + 32)             // 108576

// h exchange: B-fragment-layout image, per parity (VERIFIED layout R9-R12):
// word (kt*2+nt)*64 + l*2 + jreg : k = 16*kt + 2*(l&3) + 8*jreg, n = nt*8+(l>>2)
__device__ uint32_t g_hfrag[2][NC][2][2048];   // [parity][cluster][hi/lo][word]
__device__ float g_hT[BB * HH];

// ---------------------------------------------------------------------------
__device__ __forceinline__ uint32_t smem_u32(const void* p) {
    uint32_t a;
    asm("{ .reg .u64 t; cvta.to.shared.u64 t, %1; cvt.u32.u64 %0, t; }"
        : "=r"(a) : "l"(p));
    return a;
}
__device__ __forceinline__ float sigm(float x) { return 1.0f / (1.0f + __expf(-x)); }
__device__ __forceinline__ float tanh_fast(float x) {
    return 1.0f - 2.0f / (__expf(2.0f * x) + 1.0f);
}
__device__ __forceinline__ uint32_t split_pack(float a, float b, uint32_t& lo) {
    __half ah = __float2half_rn(a), bh = __float2half_rn(b);
    __half al = __float2half_rn(a - __half2float(ah));
    __half bl = __float2half_rn(b - __half2float(bh));
    __half2 h2 = __halves2half2(ah, bh), l2 = __halves2half2(al, bl);
    lo = *reinterpret_cast<uint32_t*>(&l2);
    return *reinterpret_cast<uint32_t*>(&h2);
}
__device__ __forceinline__ void mma16816(float* d, const uint32_t* a, const uint32_t* b) {
    asm volatile(
        "mma.sync.aligned.m16n8k16.row.col.f32.f16.f16.f32 "
        "{%0,%1,%2,%3}, {%4,%5,%6,%7}, {%8,%9}, {%0,%1,%2,%3};"
        : "+f"(d[0]), "+f"(d[1]), "+f"(d[2]), "+f"(d[3])
        : "r"(a[0]), "r"(a[1]), "r"(a[2]), "r"(a[3]), "r"(b[0]), "r"(b[1]));
}
__device__ __forceinline__ void mma6(float* acc0, float* acc1,
                                     const uint32_t* a_hi, const uint32_t* a_lo,
                                     uint2 vh0, uint2 vl0, uint2 vh1, uint2 vl1) {
    uint32_t ph0[2] = {vh0.x, vh0.y};
    uint32_t pl0[2] = {vl0.x, vl0.y};
    uint32_t ph1[2] = {vh1.x, vh1.y};
    uint32_t pl1[2] = {vl1.x, vl1.y};
    mma16816(acc0, a_hi, ph0);
    mma16816(acc0, a_hi, pl0);
    mma16816(acc0, a_lo, ph0);
    mma16816(acc1, a_hi, ph1);
    mma16816(acc1, a_hi, pl1);
    mma16816(acc1, a_lo, ph1);
}
// ---- mbarrier helpers (cluster scope) ----
#define MBAR_INIT(a, c) \
    asm volatile("mbarrier.init.shared.b64 [%0], %1;" :: "r"(a), "r"((uint32_t)(c)) : "memory")
__device__ __forceinline__ void mbar_arrive_remote(uint32_t local_mbar, uint32_t rank) {
    asm volatile(
        "{\n\t.reg .b32 ra;\n\t"
        "mapa.shared::cluster.u32 ra, %0, %1;\n\t"
        "mbarrier.arrive.release.cluster.shared::cluster.b64 _, [ra];\n\t}"
        :: "r"(local_mbar), "r"(rank) : "memory");
}
#define MBAR_WAIT_CL(mb, par) do {                                                 \
    uint32_t _m = (mb), _p = (par), _d;                                            \
    asm volatile("{\n\t.reg .pred p;\n\t"                                          \
        "mbarrier.try_wait.parity.acquire.cluster.shared::cta.b64 p, [%1], %2;\n\t"\
        "selp.b32 %0, 1, 0, p;\n\t}" : "=r"(_d) : "r"(_m), "r"(_p) : "memory");    \
    if (!_d) {                                                                     \
        asm volatile("{\n\t.reg .pred P1;\n\t"                                     \
            "WL_%=:\n\t"                                                           \
            "mbarrier.try_wait.parity.acquire.cluster.shared::cta.b64 P1, [%0], %1, 0x989680;\n\t" \
            "@P1 bra.uni WD_%=;\n\t"                                               \
            "bra.uni WL_%=;\n\t"                                                   \
            "WD_%=:\n\t}" :: "r"(_m), "r"(_p) : "memory");                         \
    }                                                                              \
} while (0)
#define CLU_ARRIVE() asm volatile("barrier.cluster.arrive.aligned;" ::: "memory")
#define CLU_WAIT()   asm volatile("barrier.cluster.wait.aligned;"   ::: "memory")

// ---------------------------------------------------------------------------
__global__ __launch_bounds__(RTH, 1) __cluster_dims__(CS, 1, 1)
void lstm_kernel(const float* __restrict__ x,
                 const float* __restrict__ Wih,
                 const float* __restrict__ Whh,
                 const float* __restrict__ bih,
                 const float* __restrict__ bhh,
                 const float* __restrict__ Wout,
                 const float* __restrict__ bout,
                 float* __restrict__ out) {
    extern __shared__ __align__(16) char smc[];
    const uint32_t sb = smem_u32(smc);
    const int tid = threadIdx.x;
    const int wid = tid >> 5, lan = tid & 31;
    const int mt = wid & 7, kh = wid >> 3;
    const int cta = blockIdx.x, q = cta / CS, r = cta % CS;
    const uint32_t mb_fullA = sb + SM_MB;
    const uint32_t mb_fullB = sb + SM_MB + 8;
    const uint32_t mb_empty = sb + SM_MB + 16;
    const uint32_t mb_myfull = (r < 4) ? mb_fullA : mb_fullB;

    uint32_t* Al  = reinterpret_cast<uint32_t*>(smc + SM_AL);
    uint32_t* Xhi = reinterpret_cast<uint32_t*>(smc + SM_XHI);
    uint32_t* Xlo = reinterpret_cast<uint32_t*>(smc + SM_XLO);
    float*    z0  = reinterpret_cast<float*>(smc + SM_Z0);
    float*    z1  = reinterpret_cast<float*>(smc + SM_Z1);
    float*    zmy = kh ? z1 : z0;

    // ---- mbarrier init + zero parity-0 h image ----
    if (tid == 0) {
        MBAR_INIT(mb_fullA, 4);   // producers 0..3, one arrive each per step
        MBAR_INIT(mb_fullB, 4);   // producers 4..7
        MBAR_INIT(mb_empty, 8);   // one arrive per consumer CTA per step
    }
    if (tid < 128)
        reinterpret_cast<uint4*>(&g_hfrag[0][q][0][0])[r * 128 + tid] =
            make_uint4(0u, 0u, 0u, 0u);

    // ---- build A fragments: hi -> registers (interleaved kts), lo -> smem ----
    uint32_t Ah[KHT][4];
#pragma unroll
    for (int ktl = 0; ktl < KHT; ktl++) {
        int kt = kh + 2 * ktl;
#pragma unroll
        for (int reg = 0; reg < 4; reg++) {
            int m  = 16 * mt + (lan >> 2) + 8 * (reg & 1);
            int kk = 16 * kt + 2 * (lan & 3) + 8 * (reg >> 1);
            int row = (m >> 5) * HH + r * 32 + (m & 31);   // gate*256 + j
            float2 v;
            if (kk < HH)
                v = *reinterpret_cast<const float2*>(&Whh[(size_t)row * HH + kk]);
            else
                v = *reinterpret_cast<const float2*>(&Wih[(size_t)row * DD + (kk - HH)]);
            uint32_t lo, hi = split_pack(v.x, v.y, lo);
            Ah[ktl][reg] = hi;
            Al[(mt * NKT + kt) * 128 + lan * 4 + reg] = lo;
        }
    }

    // ---- pointwise constants (threads 0..255 own (jp, bq)) ----
    const int tp = tid & 255;
    const int jp = tp >> 4, bq = tp & 15;
    const int j0 = r * 32 + 2 * jp;
    float bz[8];
#pragma unroll
    for (int g = 0; g < 4; g++) {
        bz[2 * g + 0] = bih[g * HH + j0] + bhh[g * HH + j0];
        bz[2 * g + 1] = bih[g * HH + j0 + 1] + bhh[g * HH + j0 + 1];
    }
    // h-writer fragment word index for (j0, j0+1) x batch bq
    const int wkt = 2 * r + (jp >> 3);
    const int wnt = bq >> 3;
    const int wl  = (bq & 7) * 4 + (jp & 3);
    const int wreg = (jp >> 2) & 1;
    const int hwi = (wkt * 2 + wnt) * 64 + wl * 2 + wreg;

    // ---- x-frag ownership (threads 0..255): words {2*tp, 2*tp+1} of 512 ----
    const int xktn = tp >> 5;
    const int xln  = tp & 31;
    const int xn   = (xktn & 1) * 8 + (xln >> 2);
    const int xd0  = (xktn >> 1) * 16 + 2 * (xln & 3);
    const float* xrow = x + ((size_t)(q * BC + xn) * TT) * DD;
    float2 pva = make_float2(0.f, 0.f), pvb = make_float2(0.f, 0.f);
    if (tid < 256) {
        float2 va = *reinterpret_cast<const float2*>(xrow + xd0);
        float2 vb = *reinterpret_cast<const float2*>(xrow + xd0 + 8);
        uint32_t lo0, hi0 = split_pack(va.x, va.y, lo0);
        uint32_t lo1, hi1 = split_pack(vb.x, vb.y, lo1);
        *reinterpret_cast<uint2*>(Xhi + 2 * tp) = make_uint2(hi0, hi1);
        *reinterpret_cast<uint2*>(Xlo + 2 * tp) = make_uint2(lo0, lo1);
        pva = *reinterpret_cast<const float2*>(xrow + DD + xd0);
        pvb = *reinterpret_cast<const float2*>(xrow + DD + xd0 + 8);
    }

    float cst[2] = {0.f, 0.f};

    __syncthreads();
    // Full cluster handshake ONCE: all mbarrier inits + zeroed h image visible
    // before any remote arrive / image read.
    CLU_ARRIVE();
    CLU_WAIT();

    for (int t = 0; t < TT; t++) {
        float acc0[4] = {0.f, 0.f, 0.f, 0.f};
        float acc1[4] = {0.f, 0.f, 0.f, 0.f};

        // ---- x-part MMAs (local; overlaps producer skew) ----
        {
            const uint32_t* xh = Xhi + (t & 1) * 512;
            const uint32_t* xl = Xlo + (t & 1) * 512;
#pragma unroll
            for (int ktl = 8; ktl < 10; ktl++) {
                int kt = kh + 2 * ktl;                       // 16..19
                int tb = ((kt - 16) * 2) * 64 + lan * 2;
                uint2 bh0 = *reinterpret_cast<const uint2*>(xh + tb);
                uint2 bh1 = *reinterpret_cast<const uint2*>(xh + tb + 64);
                uint2 bl0 = *reinterpret_cast<const uint2*>(xl + tb);
                uint2 bl1 = *reinterpret_cast<const uint2*>(xl + tb + 64);
                uint4 al4 = *reinterpret_cast<const uint4*>(
                    Al + (mt * NKT + kt) * 128 + lan * 4);
                uint32_t alr[4] = {al4.x, al4.y, al4.z, al4.w};
                mma6(acc0, acc1, Ah[ktl], alr, bh0, bl0, bh1, bl1);
            }
        }

        // ---- h-part MMAs, gated per producer group ----
        {
            const uint32_t* ghi = &g_hfrag[t & 1][q][0][0];
            const uint32_t* glo = &g_hfrag[t & 1][q][1][0];
            if (t >= 1) MBAR_WAIT_CL(mb_fullA, (t - 1) & 1);   // producers 0..3
#pragma unroll
            for (int ktl = 0; ktl < 4; ktl++) {
                int kt = kh + 2 * ktl;                         // 0..7 (group A)
                int tb = (kt * 2) * 64 + lan * 2;
                uint2 bh0 = __ldcg(reinterpret_cast<const uint2*>(ghi + tb));
                uint2 bh1 = __ldcg(reinterpret_cast<const uint2*>(ghi + tb + 64));
                uint2 bl0 = __ldcg(reinterpret_cast<const uint2*>(glo + tb));
                uint2 bl1 = __ldcg(reinterpret_cast<const uint2*>(glo + tb + 64));
                uint4 al4 = *reinterpret_cast<const uint4*>(
                    Al + (mt * NKT + kt) * 128 + lan * 4);
                uint32_t alr[4] = {al4.x, al4.y, al4.z, al4.w};
                mma6(acc0, acc1, Ah[ktl], alr, bh0, bl0, bh1, bl1);
            }
            if (t >= 1) MBAR_WAIT_CL(mb_fullB, (t - 1) & 1);   // producers 4..7
#pragma unroll
            for (int ktl = 4; ktl < 8; ktl++) {
                int kt = kh + 2 * ktl;                         // 8..15 (group B)
                int tb = (kt * 2) * 64 + lan * 2;
                uint2 bh0 = __ldcg(reinterpret_cast<const uint2*>(ghi + tb));
                uint2 bh1 = __ldcg(reinterpret_cast<const uint2*>(ghi + tb + 64));
                uint2 bl0 = __ldcg(reinterpret_cast<const uint2*>(glo + tb));
                uint2 bl1 = __ldcg(reinterpret_cast<const uint2*>(glo + tb + 64));
                uint4 al4 = *reinterpret_cast<const uint4*>(
                    Al + (mt * NKT + kt) * 128 + lan * 4);
                uint32_t alr[4] = {al4.x, al4.y, al4.z, al4.w};
                mma6(acc0, acc1, Ah[ktl], alr, bh0, bl0, bh1, bl1);
            }
        }

        // ---- park partial z (D frag layout -> z[m][b]) ----
        {
            int m0 = 16 * mt + (lan >> 2), b0 = 2 * (lan & 3);
            *reinterpret_cast<float2*>(&zmy[(m0    ) * 18 + b0    ]) = make_float2(acc0[0], acc0[1]);
            *reinterpret_cast<float2*>(&zmy[(m0 + 8) * 18 + b0    ]) = make_float2(acc0[2], acc0[3]);
            *reinterpret_cast<float2*>(&zmy[(m0    ) * 18 + b0 + 8]) = make_float2(acc1[0], acc1[1]);
            *reinterpret_cast<float2*>(&zmy[(m0 + 8) * 18 + b0 + 8]) = make_float2(acc1[2], acc1[3]);
        }
        // publish x(t+1) frags into the other buffer (before the sync)
        if (tid < 256 && t + 1 < TT) {
            uint32_t lo0, hi0 = split_pack(pva.x, pva.y, lo0);
            uint32_t lo1, hi1 = split_pack(pvb.x, pvb.y, lo1);
            uint32_t* xh = Xhi + ((t + 1) & 1) * 512;
            uint32_t* xl = Xlo + ((t + 1) & 1) * 512;
            *reinterpret_cast<uint2*>(xh + 2 * tp) = make_uint2(hi0, hi1);
            *reinterpret_cast<uint2*>(xl + 2 * tp) = make_uint2(lo0, lo1);
        }
        __syncthreads();   // z0+z1 + x(t+1) frags ready; B-reads of step t done

        // backpressure: consumers' reads of the image we're about to overwrite
        // (parity (t+1)&1, read at step t-1) must be complete.
        if (t >= 1) MBAR_WAIT_CL(mb_empty, (t - 1) & 1);

        // ---- pointwise LSTM: (j0, j0+1) x batch bq (threads 0..255) ----
        if (tid < 256) {
            float h01[2];
#pragma unroll
            for (int d = 0; d < 2; d++) {
                int mrow = 2 * jp + d;
                float zi = z0[(0 * 32 + mrow) * 18 + bq] + z1[(0 * 32 + mrow) * 18 + bq] + bz[0 + d];
                float zf = z0[(1 * 32 + mrow) * 18 + bq] + z1[(1 * 32 + mrow) * 18 + bq] + bz[2 + d];
                float zg = z0[(2 * 32 + mrow) * 18 + bq] + z1[(2 * 32 + mrow) * 18 + bq] + bz[4 + d];
                float zo = z0[(3 * 32 + mrow) * 18 + bq] + z1[(3 * 32 + mrow) * 18 + bq] + bz[6 + d];
                float cv = sigm(zf) * cst[d] + sigm(zi) * tanh_fast(zg);
                cst[d] = cv;
                h01[d] = sigm(zo) * tanh_fast(cv);
            }
            uint32_t lo, hi = split_pack(h01[0], h01[1], lo);
            __stcg(&g_hfrag[(t + 1) & 1][q][0][hwi], hi);
            __stcg(&g_hfrag[(t + 1) & 1][q][1][hwi], lo);
            if (t == TT - 1) {
                __stcg(&g_hT[(q * BC + bq) * HH + j0], h01[0]);
                __stcg(&g_hT[(q * BC + bq) * HH + j0 + 1], h01[1]);
            }
            // prefetch x(t+2)
            if (t + 2 < TT) {
                pva = *reinterpret_cast<const float2*>(xrow + (size_t)(t + 2) * DD + xd0);
                pvb = *reinterpret_cast<const float2*>(xrow + (size_t)(t + 2) * DD + xd0 + 8);
            }
        }
        __syncthreads();   // h(t) stores + this step's reads complete CTA-wide

        // ---- notify: publish h(t) (full) + reads-done (empty) to all peers ----
        if (wid == 0 && t + 1 < TT) {
            if (lan < 8)
                mbar_arrive_remote(mb_myfull, (uint32_t)lan);       // publish
            else if (lan < 16)
                mbar_arrive_remote(mb_empty, (uint32_t)(lan - 8));  // reads done
        }
    }

    // final full-cluster handshake: g_hT stores visible everywhere
    CLU_ARRIVE();
    CLU_WAIT();

    // ---- output head: CTA handles batches {2r, 2r+1}; 20 tasks / 16 warps ----
    for (int task = wid; task < 2 * NCLASS; task += 16) {
        int row = task / NCLASS, cls = task % NCLASS;
        int b = q * BC + 2 * r + row;
        float s = 0.0f;
#pragma unroll
        for (int k = lan; k < HH; k += 32)
            s += __ldcg(&g_hT[b * HH + k]) * Wout[cls * HH + k];
#pragma unroll
        for (int o = 16; o; o >>= 1) s += __shfl_xor_sync(0xffffffffu, s, o);
        if (lan == 0) out[b * NCLASS + cls] = sigm(s + bout[cls]);
    }
}

extern "C" void kernel_launch(void* const* d_in, const int* in_sizes, int n_in,
                              void* d_out, int out_size) {
    const float* x    = (const float*)d_in[0];
    const float* Wih  = (const float*)d_in[1];
    const float* Whh  = (const float*)d_in[2];
    const float* bih  = (const float*)d_in[3];
    const float* bhh  = (const float*)d_in[4];
    const float* Wout = (const float*)d_in[5];
    const float* bout = (const float*)d_in[6];
    float* out = (float*)d_out;

    cudaFuncSetAttribute(lstm_kernel,
                         cudaFuncAttributeMaxDynamicSharedMemorySize, SM_TOTAL);

    lstm_kernel<<<NC * CS, RTH, SM_TOTAL>>>(x, Wih, Whh, bih, bhh,
                                            Wout, bout, out);
}

// round 15
// speedup vs baseline: 1.0387x; 1.0387x over previous
#include <cuda_runtime.h>
#include <cuda_fp16.h>
#include <cstdint>
#include <cstddef>

// Problem sizes
#define HH     256
#define BB     256
#define TT     512
#define DD     64
#define NCLASS 10

// Topology: 16 clusters x 8 CTAs; cluster owns 16 batch rows; CTA owns 32 j.
#define CS   8
#define NC   16
#define BC   16
#define RTH  512   // 16 warps: warp = (mt = w&7, kh = w>>3)
#define NKT  20    // k-tiles: 16 for H=256 (kt 0..15), 4 for D=64 (kt 16..19)
#define KHT  10    // k-tiles per k-half warp (interleaved: kt = kh + 2*ktl)

// ---- SMEM layout (bytes) ----
// A-hi frags: [8 mt][20 kt][128 u32] = 81920
// A-lo frags: [8 mt][20 kt][128 u32] = 81920
// x frags:    [2 bufs][512 u32] hi + lo = 4096 each
// z partials: [128 m][18 floats] = 9216 each
#define SM_AH  0
#define SM_AL  (SM_AH + 8 * NKT * 512)
#define SM_XHI (SM_AL + 8 * NKT * 512)
#define SM_XLO (SM_XHI + 2 * 512 * 4)
#define SM_Z0  (SM_XLO + 2 * 512 * 4)
#define SM_Z1  (SM_Z0 + 128 * 18 * 4)
#define SM_TOTAL (SM_Z1 + 128 * 18 * 4)   // 190464

// h exchange: B-fragment-layout image, per parity (VERIFIED layout R9-R12):
// word (kt*2+nt)*64 + l*2 + jreg : k = 16*kt + 2*(l&3) + 8*jreg, n = nt*8+(l>>2)
__device__ uint32_t g_hfrag[2][NC][2][2048];   // [parity][cluster][hi/lo][word]
__device__ float g_hT[BB * HH];

// ---------------------------------------------------------------------------
__device__ __forceinline__ float sigm(float x) { return 1.0f / (1.0f + __expf(-x)); }
__device__ __forceinline__ float tanh_fast(float x) {
    return 1.0f - 2.0f / (__expf(2.0f * x) + 1.0f);
}
__device__ __forceinline__ uint32_t split_pack(float a, float b, uint32_t& lo) {
    __half ah = __float2half_rn(a), bh = __float2half_rn(b);
    __half al = __float2half_rn(a - __half2float(ah));
    __half bl = __float2half_rn(b - __half2float(bh));
    __half2 h2 = __halves2half2(ah, bh), l2 = __halves2half2(al, bl);
    lo = *reinterpret_cast<uint32_t*>(&l2);
    return *reinterpret_cast<uint32_t*>(&h2);
}
__device__ __forceinline__ void mma16816(float* d, const uint32_t* a, const uint32_t* b) {
    asm volatile(
        "mma.sync.aligned.m16n8k16.row.col.f32.f16.f16.f32 "
        "{%0,%1,%2,%3}, {%4,%5,%6,%7}, {%8,%9}, {%0,%1,%2,%3};"
        : "+f"(d[0]), "+f"(d[1]), "+f"(d[2]), "+f"(d[3])
        : "r"(a[0]), "r"(a[1]), "r"(a[2]), "r"(a[3]), "r"(b[0]), "r"(b[1]));
}
// Karatsuba k-tile (hi*hi + hi*lo + lo*hi) for both n-tiles.
__device__ __forceinline__ void mma6(float* acc0, float* acc1,
                                     const uint32_t* a_hi, const uint32_t* a_lo,
                                     uint2 vh0, uint2 vl0, uint2 vh1, uint2 vl1) {
    uint32_t ph0[2] = {vh0.x, vh0.y};
    uint32_t pl0[2] = {vl0.x, vl0.y};
    uint32_t ph1[2] = {vh1.x, vh1.y};
    uint32_t pl1[2] = {vl1.x, vl1.y};
    mma16816(acc0, a_hi, ph0);
    mma16816(acc0, a_hi, pl0);
    mma16816(acc0, a_lo, ph0);
    mma16816(acc1, a_hi, ph1);
    mma16816(acc1, a_hi, pl1);
    mma16816(acc1, a_lo, ph1);
}
#define CLU_ARRIVE() asm volatile("barrier.cluster.arrive.aligned;" ::: "memory")
#define CLU_WAIT()   asm volatile("barrier.cluster.wait.aligned;"   ::: "memory")

// ---------------------------------------------------------------------------
__global__ __launch_bounds__(RTH, 1) __cluster_dims__(CS, 1, 1)
void lstm_kernel(const float* __restrict__ x,
                 const float* __restrict__ Wih,
                 const float* __restrict__ Whh,
                 const float* __restrict__ bih,
                 const float* __restrict__ bhh,
                 const float* __restrict__ Wout,
                 const float* __restrict__ bout,
                 float* __restrict__ out) {
    extern __shared__ __align__(16) char smc[];
    const int tid = threadIdx.x;
    const int wid = tid >> 5, lan = tid & 31;
    const int mt = wid & 7, kh = wid >> 3;
    const int cta = blockIdx.x, q = cta / CS, r = cta % CS;

    uint32_t* Ahi = reinterpret_cast<uint32_t*>(smc + SM_AH);
    uint32_t* Al  = reinterpret_cast<uint32_t*>(smc + SM_AL);
    uint32_t* Xhi = reinterpret_cast<uint32_t*>(smc + SM_XHI);
    uint32_t* Xlo = reinterpret_cast<uint32_t*>(smc + SM_XLO);
    float*    z0  = reinterpret_cast<float*>(smc + SM_Z0);
    float*    z1  = reinterpret_cast<float*>(smc + SM_Z1);
    float*    zmy = kh ? z1 : z0;

    // ---- zero parity-0 h image (h0 = 0) ----
    if (tid < 128)
        reinterpret_cast<uint4*>(&g_hfrag[0][q][0][0])[r * 128 + tid] =
            make_uint4(0u, 0u, 0u, 0u);

    // ---- build A fragments: hi + lo both to smem (regs freed for B pipeline) ----
#pragma unroll
    for (int ktl = 0; ktl < KHT; ktl++) {
        int kt = kh + 2 * ktl;
#pragma unroll
        for (int reg = 0; reg < 4; reg++) {
            int m  = 16 * mt + (lan >> 2) + 8 * (reg & 1);
            int kk = 16 * kt + 2 * (lan & 3) + 8 * (reg >> 1);
            int row = (m >> 5) * HH + r * 32 + (m & 31);   // gate*256 + j
            float2 v;
            if (kk < HH)
                v = *reinterpret_cast<const float2*>(&Whh[(size_t)row * HH + kk]);
            else
                v = *reinterpret_cast<const float2*>(&Wih[(size_t)row * DD + (kk - HH)]);
            uint32_t lo, hi = split_pack(v.x, v.y, lo);
            Ahi[(mt * NKT + kt) * 128 + lan * 4 + reg] = hi;
            Al [(mt * NKT + kt) * 128 + lan * 4 + reg] = lo;
        }
    }

    // ---- pointwise constants (threads 0..255 own (jp, bq)) ----
    const int tp = tid & 255;
    const int jp = tp >> 4, bq = tp & 15;
    const int j0 = r * 32 + 2 * jp;
    float bz[8];
#pragma unroll
    for (int g = 0; g < 4; g++) {
        bz[2 * g + 0] = bih[g * HH + j0] + bhh[g * HH + j0];
        bz[2 * g + 1] = bih[g * HH + j0 + 1] + bhh[g * HH + j0 + 1];
    }
    // h-writer fragment word index for (j0, j0+1) x batch bq
    const int wkt = 2 * r + (jp >> 3);
    const int wnt = bq >> 3;
    const int wl  = (bq & 7) * 4 + (jp & 3);
    const int wreg = (jp >> 2) & 1;
    const int hwi = (wkt * 2 + wnt) * 64 + wl * 2 + wreg;

    // ---- x-frag ownership (threads 0..255): words {2*tp, 2*tp+1} of 512 ----
    const int xktn = tp >> 5;
    const int xln  = tp & 31;
    const int xn   = (xktn & 1) * 8 + (xln >> 2);
    const int xd0  = (xktn >> 1) * 16 + 2 * (xln & 3);
    const float* xrow = x + ((size_t)(q * BC + xn) * TT) * DD;
    float2 pva = make_float2(0.f, 0.f), pvb = make_float2(0.f, 0.f);
    if (tid < 256) {
        float2 va = *reinterpret_cast<const float2*>(xrow + xd0);
        float2 vb = *reinterpret_cast<const float2*>(xrow + xd0 + 8);
        uint32_t lo0, hi0 = split_pack(va.x, va.y, lo0);
        uint32_t lo1, hi1 = split_pack(vb.x, vb.y, lo1);
        *reinterpret_cast<uint2*>(Xhi + 2 * tp) = make_uint2(hi0, hi1);
        *reinterpret_cast<uint2*>(Xlo + 2 * tp) = make_uint2(lo0, lo1);
        pva = *reinterpret_cast<const float2*>(xrow + DD + xd0);
        pvb = *reinterpret_cast<const float2*>(xrow + DD + xd0 + 8);
    }

    float cst[2] = {0.f, 0.f};

    __syncthreads();
    CLU_ARRIVE();   // publish zeroed h image

    for (int t = 0; t < TT; t++) {
        float acc0[4] = {0.f, 0.f, 0.f, 0.f};
        float acc1[4] = {0.f, 0.f, 0.f, 0.f};

        // ---- x-part MMAs (local; hides cluster barrier skew) ----
        {
            const uint32_t* xh = Xhi + (t & 1) * 512;
            const uint32_t* xl = Xlo + (t & 1) * 512;
#pragma unroll
            for (int ktl = 8; ktl < 10; ktl++) {
                int kt = kh + 2 * ktl;                       // 16..19
                int tb = ((kt - 16) * 2) * 64 + lan * 2;
                uint2 bh0 = *reinterpret_cast<const uint2*>(xh + tb);
                uint2 bh1 = *reinterpret_cast<const uint2*>(xh + tb + 64);
                uint2 bl0 = *reinterpret_cast<const uint2*>(xl + tb);
                uint2 bl1 = *reinterpret_cast<const uint2*>(xl + tb + 64);
                uint4 ah4 = *reinterpret_cast<const uint4*>(
                    Ahi + (mt * NKT + kt) * 128 + lan * 4);
                uint4 al4 = *reinterpret_cast<const uint4*>(
                    Al + (mt * NKT + kt) * 128 + lan * 4);
                uint32_t ahr[4] = {ah4.x, ah4.y, ah4.z, ah4.w};
                uint32_t alr[4] = {al4.x, al4.y, al4.z, al4.w};
                mma6(acc0, acc1, ahr, alr, bh0, bl0, bh1, bl1);
            }
        }

        CLU_WAIT();   // peers' h(t-1) frags visible

        // ---- h-part MMAs: B from L2 via a 4-deep rotating prefetch pipeline ----
        {
            const uint32_t* ghi = &g_hfrag[t & 1][q][0][0];
            const uint32_t* glo = &g_hfrag[t & 1][q][1][0];
            uint2 bb[4][4];    // [slot][{h0, h1, l0, l1}]
#pragma unroll
            for (int i = 0; i < 4; i++) {
                int kt = kh + 2 * i;
                int tb = (kt * 2) * 64 + lan * 2;
                bb[i][0] = __ldcg(reinterpret_cast<const uint2*>(ghi + tb));
                bb[i][1] = __ldcg(reinterpret_cast<const uint2*>(ghi + tb + 64));
                bb[i][2] = __ldcg(reinterpret_cast<const uint2*>(glo + tb));
                bb[i][3] = __ldcg(reinterpret_cast<const uint2*>(glo + tb + 64));
            }
#pragma unroll
            for (int ktl = 0; ktl < 8; ktl++) {
                int sl = ktl & 3;
                int kt = kh + 2 * ktl;
                uint2 bh0 = bb[sl][0], bh1 = bb[sl][1];
                uint2 bl0 = bb[sl][2], bl1 = bb[sl][3];
                if (ktl + 4 < 8) {
                    int kt2 = kh + 2 * (ktl + 4);
                    int tb2 = (kt2 * 2) * 64 + lan * 2;
                    bb[sl][0] = __ldcg(reinterpret_cast<const uint2*>(ghi + tb2));
                    bb[sl][1] = __ldcg(reinterpret_cast<const uint2*>(ghi + tb2 + 64));
                    bb[sl][2] = __ldcg(reinterpret_cast<const uint2*>(glo + tb2));
                    bb[sl][3] = __ldcg(reinterpret_cast<const uint2*>(glo + tb2 + 64));
                }
                uint4 ah4 = *reinterpret_cast<const uint4*>(
                    Ahi + (mt * NKT + kt) * 128 + lan * 4);
                uint4 al4 = *reinterpret_cast<const uint4*>(
                    Al + (mt * NKT + kt) * 128 + lan * 4);
                uint32_t ahr[4] = {ah4.x, ah4.y, ah4.z, ah4.w};
                uint32_t alr[4] = {al4.x, al4.y, al4.z, al4.w};
                mma6(acc0, acc1, ahr, alr, bh0, bl0, bh1, bl1);
            }
        }

        // ---- park partial z (D frag layout -> z[m][b]) ----
        {
            int m0 = 16 * mt + (lan >> 2), b0 = 2 * (lan & 3);
            *reinterpret_cast<float2*>(&zmy[(m0    ) * 18 + b0    ]) = make_float2(acc0[0], acc0[1]);
            *reinterpret_cast<float2*>(&zmy[(m0 + 8) * 18 + b0    ]) = make_float2(acc0[2], acc0[3]);
            *reinterpret_cast<float2*>(&zmy[(m0    ) * 18 + b0 + 8]) = make_float2(acc1[0], acc1[1]);
            *reinterpret_cast<float2*>(&zmy[(m0 + 8) * 18 + b0 + 8]) = make_float2(acc1[2], acc1[3]);
        }
        // publish x(t+1) frags into the other buffer (before the sync)
        if (tid < 256 && t + 1 < TT) {
            uint32_t lo0, hi0 = split_pack(pva.x, pva.y, lo0);
            uint32_t lo1, hi1 = split_pack(pvb.x, pvb.y, lo1);
            uint32_t* xh = Xhi + ((t + 1) & 1) * 512;
            uint32_t* xl = Xlo + ((t + 1) & 1) * 512;
            *reinterpret_cast<uint2*>(xh + 2 * tp) = make_uint2(hi0, hi1);
            *reinterpret_cast<uint2*>(xl + 2 * tp) = make_uint2(lo0, lo1);
        }
        __syncthreads();   // z0+z1 + x(t+1) frags ready

        // ---- pointwise LSTM: (j0, j0+1) x batch bq (threads 0..255) ----
        if (tid < 256) {
            float h01[2];
#pragma unroll
            for (int d = 0; d < 2; d++) {
                int mrow = 2 * jp + d;
                float zi = z0[(0 * 32 + mrow) * 18 + bq] + z1[(0 * 32 + mrow) * 18 + bq] + bz[0 + d];
                float zf = z0[(1 * 32 + mrow) * 18 + bq] + z1[(1 * 32 + mrow) * 18 + bq] + bz[2 + d];
                float zg = z0[(2 * 32 + mrow) * 18 + bq] + z1[(2 * 32 + mrow) * 18 + bq] + bz[4 + d];
                float zo = z0[(3 * 32 + mrow) * 18 + bq] + z1[(3 * 32 + mrow) * 18 + bq] + bz[6 + d];
                float cv = sigm(zf) * cst[d] + sigm(zi) * tanh_fast(zg);
                cst[d] = cv;
                h01[d] = sigm(zo) * tanh_fast(cv);
            }
            uint32_t lo, hi = split_pack(h01[0], h01[1], lo);
            __stcg(&g_hfrag[(t + 1) & 1][q][0][hwi], hi);
            __stcg(&g_hfrag[(t + 1) & 1][q][1][hwi], lo);
            if (t == TT - 1) {
                __stcg(&g_hT[(q * BC + bq) * HH + j0], h01[0]);
                __stcg(&g_hT[(q * BC + bq) * HH + j0 + 1], h01[1]);
            }
            // prefetch x(t+2)
            if (t + 2 < TT) {
                pva = *reinterpret_cast<const float2*>(xrow + (size_t)(t + 2) * DD + xd0);
                pvb = *reinterpret_cast<const float2*>(xrow + (size_t)(t + 2) * DD + xd0 + 8);
            }
        }
        CLU_ARRIVE();   // release h(t)
    }
    CLU_WAIT();

    // ---- output head: CTA handles batches {2r, 2r+1}; 20 tasks / 16 warps ----
    for (int task = wid; task < 2 * NCLASS; task += 16) {
        int row = task / NCLASS, cls = task % NCLASS;
        int b = q * BC + 2 * r + row;
        float s = 0.0f;
#pragma unroll
        for (int k = lan; k < HH; k += 32)
            s += __ldcg(&g_hT[b * HH + k]) * Wout[cls * HH + k];
#pragma unroll
        for (int o = 16; o; o >>= 1) s += __shfl_xor_sync(0xffffffffu, s, o);
        if (lan == 0) out[b * NCLASS + cls] = sigm(s + bout[cls]);
    }
}

extern "C" void kernel_launch(void* const* d_in, const int* in_sizes, int n_in,
                              void* d_out, int out_size) {
    const float* x    = (const float*)d_in[0];
    const float* Wih  = (const float*)d_in[1];
    const float* Whh  = (const float*)d_in[2];
    const float* bih  = (const float*)d_in[3];
    const float* bhh  = (const float*)d_in[4];
    const float* Wout = (const float*)d_in[5];
    const float* bout = (const float*)d_in[6];
    float* out = (float*)d_out;

    cudaFuncSetAttribute(lstm_kernel,
                         cudaFuncAttributeMaxDynamicSharedMemorySize, SM_TOTAL);

    lstm_kernel<<<NC * CS, RTH, SM_TOTAL>>>(x, Wih, Whh, bih, bhh,
                                            Wout, bout, out);
}

// round 16
// speedup vs baseline: 1.0640x; 1.0243x over previous
#include <cuda_runtime.h>
#include <cuda_fp16.h>
#include <cstdint>
#include <cstddef>

// Problem sizes
#define HH     256
#define BB     256
#define TT     512
#define DD     64
#define NCLASS 10

// Topology: 16 clusters x 8 CTAs; cluster owns 16 batch rows; CTA owns 32 j.
#define CS   8
#define NC   16
#define BC   16
#define RTH  512   // 16 warps: warp = (mt = w&7, kh = w>>3)
#define NKT  20    // k-tiles: 16 for H=256 (kt 0..15), 4 for D=64 (kt 16..19)
#define KHT  10    // k-tiles per k-half warp (interleaved: kt = kh + 2*ktl)

// ---- SMEM layout (bytes) ----
#define SM_AL  0
#define SM_XHI (SM_AL + 8 * NKT * 512)
#define SM_XLO (SM_XHI + 2 * 512 * 4)
#define SM_Z0  (SM_XLO + 2 * 512 * 4)
#define SM_Z1  (SM_Z0 + 128 * 18 * 4)
#define SM_TOTAL (SM_Z1 + 128 * 18 * 4)   // 120832

// h exchange image, INTERLEAVED hi/lo (new in R16):
//   u32 index 2*word+0 = hi, 2*word+1 = lo, where `word` is the VERIFIED
//   R9-R12 B-fragment index: word (kt*2+nt)*64 + l*2 + jreg,
//   k = 16*kt + 2*(l&3) + 8*jreg (k,k+1 packed in the u16 halves), n = nt*8+(l>>2)
__device__ uint32_t g_hfrag[2][NC][4096];
__device__ float g_hT[BB * HH];

// ---------------------------------------------------------------------------
__device__ __forceinline__ float sigm(float x) { return 1.0f / (1.0f + __expf(-x)); }
__device__ __forceinline__ float tanh_fast(float x) {
    return 1.0f - 2.0f / (__expf(2.0f * x) + 1.0f);
}
__device__ __forceinline__ uint32_t split_pack(float a, float b, uint32_t& lo) {
    __half ah = __float2half_rn(a), bh = __float2half_rn(b);
    __half al = __float2half_rn(a - __half2float(ah));
    __half bl = __float2half_rn(b - __half2float(bh));
    __half2 h2 = __halves2half2(ah, bh), l2 = __halves2half2(al, bl);
    lo = *reinterpret_cast<uint32_t*>(&l2);
    return *reinterpret_cast<uint32_t*>(&h2);
}
__device__ __forceinline__ void mma16816(float* d, const uint32_t* a, const uint32_t* b) {
    asm volatile(
        "mma.sync.aligned.m16n8k16.row.col.f32.f16.f16.f32 "
        "{%0,%1,%2,%3}, {%4,%5,%6,%7}, {%8,%9}, {%0,%1,%2,%3};"
        : "+f"(d[0]), "+f"(d[1]), "+f"(d[2]), "+f"(d[3])
        : "r"(a[0]), "r"(a[1]), "r"(a[2]), "r"(a[3]), "r"(b[0]), "r"(b[1]));
}
// Karatsuba k-tile (hi*hi + hi*lo + lo*hi) for both n-tiles.
__device__ __forceinline__ void mma6(float* acc0, float* acc1,
                                     const uint32_t* a_hi, const uint32_t* a_lo,
                                     uint2 vh0, uint2 vl0, uint2 vh1, uint2 vl1) {
    uint32_t ph0[2] = {vh0.x, vh0.y};
    uint32_t pl0[2] = {vl0.x, vl0.y};
    uint32_t ph1[2] = {vh1.x, vh1.y};
    uint32_t pl1[2] = {vl1.x, vl1.y};
    mma16816(acc0, a_hi, ph0);
    mma16816(acc0, a_hi, pl0);
    mma16816(acc0, a_lo, ph0);
    mma16816(acc1, a_hi, ph1);
    mma16816(acc1, a_hi, pl1);
    mma16816(acc1, a_lo, ph1);
}
__device__ __forceinline__ void stg_v2(uint32_t* p, uint32_t a, uint32_t b) {
    asm volatile("st.global.cg.v2.u32 [%0], {%1, %2};"
                 :: "l"(p), "r"(a), "r"(b) : "memory");
}
#define CLU_ARRIVE() asm volatile("barrier.cluster.arrive.aligned;" ::: "memory")
#define CLU_WAIT()   asm volatile("barrier.cluster.wait.aligned;"   ::: "memory")

// ---------------------------------------------------------------------------
__global__ __launch_bounds__(RTH, 1) __cluster_dims__(CS, 1, 1)
void lstm_kernel(const float* __restrict__ x,
                 const float* __restrict__ Wih,
                 const float* __restrict__ Whh,
                 const float* __restrict__ bih,
                 const float* __restrict__ bhh,
                 const float* __restrict__ Wout,
                 const float* __restrict__ bout,
                 float* __restrict__ out) {
    extern __shared__ __align__(16) char smc[];
    const int tid = threadIdx.x;
    const int wid = tid >> 5, lan = tid & 31;
    const int mt = wid & 7, kh = wid >> 3;
    const int cta = blockIdx.x, q = cta / CS, r = cta % CS;

    uint32_t* Al  = reinterpret_cast<uint32_t*>(smc + SM_AL);
    uint32_t* Xhi = reinterpret_cast<uint32_t*>(smc + SM_XHI);
    uint32_t* Xlo = reinterpret_cast<uint32_t*>(smc + SM_XLO);
    float*    z0  = reinterpret_cast<float*>(smc + SM_Z0);
    float*    z1  = reinterpret_cast<float*>(smc + SM_Z1);
    float*    zmy = kh ? z1 : z0;

    // ---- zero parity-0 h image (h0 = 0): 1024 uint4 per cluster ----
    if (tid < 128)
        reinterpret_cast<uint4*>(&g_hfrag[0][q][0])[r * 128 + tid] =
            make_uint4(0u, 0u, 0u, 0u);

    // ---- build A fragments: hi -> registers (interleaved kts), lo -> smem ----
    uint32_t Ah[KHT][4];
#pragma unroll
    for (int ktl = 0; ktl < KHT; ktl++) {
        int kt = kh + 2 * ktl;
#pragma unroll
        for (int reg = 0; reg < 4; reg++) {
            int m  = 16 * mt + (lan >> 2) + 8 * (reg & 1);
            int kk = 16 * kt + 2 * (lan & 3) + 8 * (reg >> 1);
            int row = (m >> 5) * HH + r * 32 + (m & 31);   // gate*256 + j
            float2 v;
            if (kk < HH)
                v = *reinterpret_cast<const float2*>(&Whh[(size_t)row * HH + kk]);
            else
                v = *reinterpret_cast<const float2*>(&Wih[(size_t)row * DD + (kk - HH)]);
            uint32_t lo, hi = split_pack(v.x, v.y, lo);
            Ah[ktl][reg] = hi;
            Al[(mt * NKT + kt) * 128 + lan * 4 + reg] = lo;
        }
    }

    // ---- pointwise constants (threads 0..255 own (jp, bq)) ----
    const int tp = tid & 255;
    const int jp = tp >> 4, bq = tp & 15;
    const int j0 = r * 32 + 2 * jp;
    float bz[8];
#pragma unroll
    for (int g = 0; g < 4; g++) {
        bz[2 * g + 0] = bih[g * HH + j0] + bhh[g * HH + j0];
        bz[2 * g + 1] = bih[g * HH + j0 + 1] + bhh[g * HH + j0 + 1];
    }
    // h-writer fragment word index for (j0, j0+1) x batch bq
    const int wkt = 2 * r + (jp >> 3);
    const int wnt = bq >> 3;
    const int wl  = (bq & 7) * 4 + (jp & 3);
    const int wreg = (jp >> 2) & 1;
    const int hwi = (wkt * 2 + wnt) * 64 + wl * 2 + wreg;

    // ---- x-frag ownership (threads 0..255): words {2*tp, 2*tp+1} of 512 ----
    const int xktn = tp >> 5;
    const int xln  = tp & 31;
    const int xn   = (xktn & 1) * 8 + (xln >> 2);
    const int xd0  = (xktn >> 1) * 16 + 2 * (xln & 3);
    const float* xrow = x + ((size_t)(q * BC + xn) * TT) * DD;
    float2 pva = make_float2(0.f, 0.f), pvb = make_float2(0.f, 0.f);
    if (tid < 256) {
        float2 va = *reinterpret_cast<const float2*>(xrow + xd0);
        float2 vb = *reinterpret_cast<const float2*>(xrow + xd0 + 8);
        uint32_t lo0, hi0 = split_pack(va.x, va.y, lo0);
        uint32_t lo1, hi1 = split_pack(vb.x, vb.y, lo1);
        *reinterpret_cast<uint2*>(Xhi + 2 * tp) = make_uint2(hi0, hi1);
        *reinterpret_cast<uint2*>(Xlo + 2 * tp) = make_uint2(lo0, lo1);
        pva = *reinterpret_cast<const float2*>(xrow + DD + xd0);
        pvb = *reinterpret_cast<const float2*>(xrow + DD + xd0 + 8);
    }

    float cst[2] = {0.f, 0.f};

    __syncthreads();
    CLU_ARRIVE();   // publish zeroed h image

    for (int t = 0; t < TT; t++) {
        float acc0[4] = {0.f, 0.f, 0.f, 0.f};
        float acc1[4] = {0.f, 0.f, 0.f, 0.f};

        // ---- x-part MMAs (local; hides cluster barrier skew) ----
        {
            const uint32_t* xh = Xhi + (t & 1) * 512;
            const uint32_t* xl = Xlo + (t & 1) * 512;
#pragma unroll
            for (int ktl = 8; ktl < 10; ktl++) {
                int kt = kh + 2 * ktl;                       // 16..19
                int tb = ((kt - 16) * 2) * 64 + lan * 2;
                uint2 bh0 = *reinterpret_cast<const uint2*>(xh + tb);
                uint2 bh1 = *reinterpret_cast<const uint2*>(xh + tb + 64);
                uint2 bl0 = *reinterpret_cast<const uint2*>(xl + tb);
                uint2 bl1 = *reinterpret_cast<const uint2*>(xl + tb + 64);
                uint4 al4 = *reinterpret_cast<const uint4*>(
                    Al + (mt * NKT + kt) * 128 + lan * 4);
                uint32_t alr[4] = {al4.x, al4.y, al4.z, al4.w};
                mma6(acc0, acc1, Ah[ktl], alr, bh0, bl0, bh1, bl1);
            }
        }

        CLU_WAIT();   // peers' h(t-1) frags visible

        // ---- h-part MMAs: interleaved image -> 2x LDG.128 per kt ----
        {
            const uint32_t* gim = &g_hfrag[t & 1][q][0];
#pragma unroll
            for (int ktl = 0; ktl < 8; ktl++) {
                int kt = kh + 2 * ktl;
                int tb = (kt * 2) * 64 + lan * 2;            // old word index
                uint4 v0 = __ldcg(reinterpret_cast<const uint4*>(gim + 2 * tb));
                uint4 v1 = __ldcg(reinterpret_cast<const uint4*>(gim + 2 * (tb + 64)));
                uint2 bh0 = make_uint2(v0.x, v0.z), bl0 = make_uint2(v0.y, v0.w);
                uint2 bh1 = make_uint2(v1.x, v1.z), bl1 = make_uint2(v1.y, v1.w);
                uint4 al4 = *reinterpret_cast<const uint4*>(
                    Al + (mt * NKT + kt) * 128 + lan * 4);
                uint32_t alr[4] = {al4.x, al4.y, al4.z, al4.w};
                mma6(acc0, acc1, Ah[ktl], alr, bh0, bl0, bh1, bl1);
            }
        }

        // ---- park partial z (D frag layout -> z[m][b]) ----
        {
            int m0 = 16 * mt + (lan >> 2), b0 = 2 * (lan & 3);
            *reinterpret_cast<float2*>(&zmy[(m0    ) * 18 + b0    ]) = make_float2(acc0[0], acc0[1]);
            *reinterpret_cast<float2*>(&zmy[(m0 + 8) * 18 + b0    ]) = make_float2(acc0[2], acc0[3]);
            *reinterpret_cast<float2*>(&zmy[(m0    ) * 18 + b0 + 8]) = make_float2(acc1[0], acc1[1]);
            *reinterpret_cast<float2*>(&zmy[(m0 + 8) * 18 + b0 + 8]) = make_float2(acc1[2], acc1[3]);
        }
        // publish x(t+1) frags into the other buffer (before the sync)
        if (tid < 256 && t + 1 < TT) {
            uint32_t lo0, hi0 = split_pack(pva.x, pva.y, lo0);
            uint32_t lo1, hi1 = split_pack(pvb.x, pvb.y, lo1);
            uint32_t* xh = Xhi + ((t + 1) & 1) * 512;
            uint32_t* xl = Xlo + ((t + 1) & 1) * 512;
            *reinterpret_cast<uint2*>(xh + 2 * tp) = make_uint2(hi0, hi1);
            *reinterpret_cast<uint2*>(xl + 2 * tp) = make_uint2(lo0, lo1);
        }
        __syncthreads();   // z0+z1 + x(t+1) frags ready

        // ---- pointwise LSTM: (j0, j0+1) x batch bq (threads 0..255) ----
        if (tid < 256) {
            float h01[2];
#pragma unroll
            for (int d = 0; d < 2; d++) {
                int mrow = 2 * jp + d;
                float zi = z0[(0 * 32 + mrow) * 18 + bq] + z1[(0 * 32 + mrow) * 18 + bq] + bz[0 + d];
                float zf = z0[(1 * 32 + mrow) * 18 + bq] + z1[(1 * 32 + mrow) * 18 + bq] + bz[2 + d];
                float zg = z0[(2 * 32 + mrow) * 18 + bq] + z1[(2 * 32 + mrow) * 18 + bq] + bz[4 + d];
                float zo = z0[(3 * 32 + mrow) * 18 + bq] + z1[(3 * 32 + mrow) * 18 + bq] + bz[6 + d];
                float cv = sigm(zf) * cst[d] + sigm(zi) * tanh_fast(zg);
                cst[d] = cv;
                h01[d] = sigm(zo) * tanh_fast(cv);
            }
            uint32_t lo, hi = split_pack(h01[0], h01[1], lo);
            stg_v2(&g_hfrag[(t + 1) & 1][q][2 * hwi], hi, lo);   // one STG.64
            if (t == TT - 1) {
                __stcg(&g_hT[(q * BC + bq) * HH + j0], h01[0]);
                __stcg(&g_hT[(q * BC + bq) * HH + j0 + 1], h01[1]);
            }
            // prefetch x(t+2)
            if (t + 2 < TT) {
                pva = *reinterpret_cast<const float2*>(xrow + (size_t)(t + 2) * DD + xd0);
                pvb = *reinterpret_cast<const float2*>(xrow + (size_t)(t + 2) * DD + xd0 + 8);
            }
        }
        CLU_ARRIVE();   // release h(t)
    }
    CLU_WAIT();

    // ---- output head: CTA handles batches {2r, 2r+1}; 20 tasks / 16 warps ----
    for (int task = wid; task < 2 * NCLASS; task += 16) {
        int row = task / NCLASS, cls = task % NCLASS;
        int b = q * BC + 2 * r + row;
        float s = 0.0f;
#pragma unroll
        for (int k = lan; k < HH; k += 32)
            s += __ldcg(&g_hT[b * HH + k]) * Wout[cls * HH + k];
#pragma unroll
        for (int o = 16; o; o >>= 1) s += __shfl_xor_sync(0xffffffffu, s, o);
        if (lan == 0) out[b * NCLASS + cls] = sigm(s + bout[cls]);
    }
}

extern "C" void kernel_launch(void* const* d_in, const int* in_sizes, int n_in,
                              void* d_out, int out_size) {
    const float* x    = (const float*)d_in[0];
    const float* Wih  = (const float*)d_in[1];
    const float* Whh  = (const float*)d_in[2];
    const float* bih  = (const float*)d_in[3];
    const float* bhh  = (const float*)d_in[4];
    const float* Wout = (const float*)d_in[5];
    const float* bout = (const float*)d_in[6];
    float* out = (float*)d_out;

    cudaFuncSetAttribute(lstm_kernel,
                         cudaFuncAttributeMaxDynamicSharedMemorySize, SM_TOTAL);

    lstm_kernel<<<NC * CS, RTH, SM_TOTAL>>>(x, Wih, Whh, bih, bhh,
                                            Wout, bout, out);
}